// round 1
// baseline (speedup 1.0000x reference)
#include <cuda_runtime.h>

// Problem constants
#define D_ 4
#define R_ 32
#define F_ 8
#define U_ 64
#define B_ 512
#define KSZ (D_*R_*R_*F_*U_)   // 2,097,152 floats = 8 MB

// Transposed kernel layout: Kt[u][f][d][j*32+k], contiguous per (u,f,d)
__device__ float g_Kt[KSZ];

// Prologue: K[d,j,k,f,u] (src index = ((d*1024 + jk)*8 + f)*64 + u)
//        -> Kt[((u*8+f)*4+d)*1024 + jk]
// Iterate in destination order: writes fully coalesced, reads scattered but
// L2-resident (8 MB working set).
__global__ __launch_bounds__(256) void kt_transpose(const float* __restrict__ K) {
    int e = blockIdx.x * blockDim.x + threadIdx.x;   // dst index
    int jk = e & 1023;
    int d  = (e >> 10) & 3;
    int f  = (e >> 12) & 7;
    int u  = e >> 15;
    g_Kt[e] = K[((d * 1024 + jk) * 8 + f) * 64 + u];
}

// Main: one warp per (b,u). Lane i owns row i of the running product M in
// 32 registers. Each T_f is built into per-warp smem (coalesced float4 loads
// from Kt), then M = M @ T_f via broadcast LDS.128 of T rows. Final step is
// the trace contraction only (no full matmul), then a warp reduction.
__global__ __launch_bounds__(128) void ring_chain(const float* __restrict__ X,
                                                  float* __restrict__ out) {
    __shared__ float4 Tsm[4][R_*R_/4];   // 4 warps * 4 KB
    const int warp = threadIdx.x >> 5;
    const int lane = threadIdx.x & 31;
    const int gw = (blockIdx.x << 2) | warp;   // 0 .. 32767
    const int u = gw & 63;
    const int b = gw >> 6;

    // X[b, f, d] flattened: lane <-> f*4+d  (32 floats per b)
    const float xv = X[b * 32 + lane];
    const float4* __restrict__ Ku =
        (const float4*)(g_Kt + (size_t)u * (F_ * D_ * R_ * R_));
    float4* Tw = Tsm[warp];

    float m[R_];

    #pragma unroll 1
    for (int f = 0; f < F_; f++) {
        // ---- build T_f into smem: T[jk] = sum_d x[f][d] * Kt[u][f][d][jk]
        const float4* Kf = Ku + f * (D_ * R_ * R_ / 4);
        const float x0 = __shfl_sync(0xffffffffu, xv, f * 4 + 0);
        const float x1 = __shfl_sync(0xffffffffu, xv, f * 4 + 1);
        const float x2 = __shfl_sync(0xffffffffu, xv, f * 4 + 2);
        const float x3 = __shfl_sync(0xffffffffu, xv, f * 4 + 3);
        __syncwarp();   // previous iteration's reads of Tw are done
        #pragma unroll
        for (int t = 0; t < 8; t++) {
            const int idx = t * 32 + lane;           // coalesced float4
            const float4 a  = Kf[idx];
            const float4 bb = Kf[256 + idx];
            const float4 c  = Kf[512 + idx];
            const float4 dd = Kf[768 + idx];
            float4 r;
            r.x = x0 * a.x + x1 * bb.x + x2 * c.x + x3 * dd.x;
            r.y = x0 * a.y + x1 * bb.y + x2 * c.y + x3 * dd.y;
            r.z = x0 * a.z + x1 * bb.z + x2 * c.z + x3 * dd.z;
            r.w = x0 * a.w + x1 * bb.w + x2 * c.w + x3 * dd.w;
            Tw[idx] = r;
        }
        __syncwarp();   // T_f visible to all lanes

        if (f == 0) {
            // M = T_0 : lane i loads row i
            #pragma unroll
            for (int kv = 0; kv < 8; kv++) {
                const float4 t4 = Tw[lane * 8 + kv];
                m[4*kv + 0] = t4.x; m[4*kv + 1] = t4.y;
                m[4*kv + 2] = t4.z; m[4*kv + 3] = t4.w;
            }
        } else if (f < F_ - 1) {
            // M = M @ T_f : acc[k] += m[j] * T[j][k], T rows broadcast via smem
            float acc[R_];
            #pragma unroll
            for (int k = 0; k < R_; k++) acc[k] = 0.f;
            #pragma unroll
            for (int j = 0; j < R_; j++) {
                const float mj = m[j];
                #pragma unroll
                for (int kv = 0; kv < 8; kv++) {
                    const float4 t4 = Tw[j * 8 + kv];   // broadcast, no conflicts
                    acc[4*kv + 0] += mj * t4.x;
                    acc[4*kv + 1] += mj * t4.y;
                    acc[4*kv + 2] += mj * t4.z;
                    acc[4*kv + 3] += mj * t4.w;
                }
            }
            #pragma unroll
            for (int k = 0; k < R_; k++) m[k] = acc[k];
        } else {
            // trace(M @ T_7) = sum_i sum_j M[i,j] * T7[j,i]
            // lane i: partial = sum_j m[j] * T[j][i]  (column read, stride 32
            // floats -> bank = lane -> conflict-free)
            const float* Ts = (const float*)Tw;
            float p = 0.f;
            #pragma unroll
            for (int j = 0; j < R_; j++) p += m[j] * Ts[j * 32 + lane];
            #pragma unroll
            for (int o = 16; o; o >>= 1)
                p += __shfl_down_sync(0xffffffffu, p, o);
            if (lane == 0) out[b * 64 + u] = p;
        }
    }
}

extern "C" void kernel_launch(void* const* d_in, const int* in_sizes, int n_in,
                              void* d_out, int out_size) {
    // metadata order: X (16384 floats), kernel (2097152 floats). Be defensive.
    const float* X = (const float*)d_in[0];
    const float* K = (const float*)d_in[1];
    if (in_sizes[0] != B_ * F_ * D_) {
        X = (const float*)d_in[1];
        K = (const float*)d_in[0];
    }
    kt_transpose<<<KSZ / 256, 256>>>(K);
    ring_chain<<<(B_ * U_) / 4, 128>>>(X, (float*)d_out);
}

// round 2
// speedup vs baseline: 2.0904x; 2.0904x over previous
#include <cuda_runtime.h>

// Problem constants
#define D_ 4
#define R_ 32
#define F_ 8
#define U_ 64
#define B_ 512

typedef unsigned long long ull;

// ---------- packed f32x2 helpers (SASS FFMA2) ----------
static __device__ __forceinline__ ull pk2(float lo, float hi) {
    ull r; asm("mov.b64 %0, {%1, %2};" : "=l"(r) : "f"(lo), "f"(hi)); return r;
}
static __device__ __forceinline__ void upk2(ull v, float& lo, float& hi) {
    asm("mov.b64 {%0, %1}, %2;" : "=f"(lo), "=f"(hi) : "l"(v));
}
static __device__ __forceinline__ ull fma2_(ull a, ull b, ull c) {
    ull d; asm("fma.rn.f32x2 %0, %1, %2, %3;" : "=l"(d) : "l"(a), "l"(b), "l"(c)); return d;
}
static __device__ __forceinline__ ull mul2_(ull a, ull b) {
    ull d; asm("mul.rn.f32x2 %0, %1, %2;" : "=l"(d) : "l"(a), "l"(b)); return d;
}

// Pair-merged kernel products:
// g_KK[u][p][c=(d0*4+d1)][j*32+k] = sum_j' K[d0,j,j',2p,u] * K[d1,j',k,2p+1,u]
__device__ float g_KK[U_ * 4 * 16 * 1024];   // 16 MB

// ---------------------------------------------------------------------------
// Precompute: 256 blocks = (u, p); 256 threads. Stage the 8 source 32x32
// matrices in smem (A pitch-33 for conflict-free row reads, B row-major for
// broadcast), each warp computes 2 of the 16 (d0,d1) products.
// ---------------------------------------------------------------------------
__global__ __launch_bounds__(256) void kk_precompute(const float* __restrict__ K) {
    __shared__ float As[4][33 * 32];
    __shared__ float Bs[4][1024];
    const int u = blockIdx.x >> 2;
    const int p = blockIdx.x & 3;
    const int tid = threadIdx.x;

    for (int d = 0; d < 4; d++) {
        for (int e = tid; e < 1024; e += 256) {
            As[d][(e >> 5) * 33 + (e & 31)] = K[((d * 1024 + e) * 8 + 2 * p) * 64 + u];
            Bs[d][e]                        = K[((d * 1024 + e) * 8 + 2 * p + 1) * 64 + u];
        }
    }
    __syncthreads();

    const int w = tid >> 5, lane = tid & 31;
    const int i = lane;
    #pragma unroll 1
    for (int cc = 0; cc < 2; cc++) {
        const int c = w * 2 + cc;
        const int d0 = c >> 2, d1 = c & 3;
        ull acc[16];
        #pragma unroll
        for (int q = 0; q < 16; q++) acc[q] = 0ull;
        const float* arow = &As[d0][i * 33];
        const ulonglong2* bmat = (const ulonglong2*)Bs[d1];
        #pragma unroll
        for (int j = 0; j < 32; j++) {
            const ull a2 = pk2(arow[j], arow[j]);
            #pragma unroll
            for (int q = 0; q < 8; q++) {
                const ulonglong2 bv = bmat[j * 8 + q];   // broadcast
                acc[2 * q]     = fma2_(a2, bv.x, acc[2 * q]);
                acc[2 * q + 1] = fma2_(a2, bv.y, acc[2 * q + 1]);
            }
        }
        float4* dst = (float4*)(g_KK + (((u * 4 + p) * 16 + c) * 1024) + i * 32);
        #pragma unroll
        for (int q = 0; q < 8; q++) {
            float4 o;
            upk2(acc[2 * q],     o.x, o.y);
            upk2(acc[2 * q + 1], o.z, o.w);
            dst[q] = o;
        }
    }
}

// ---------------------------------------------------------------------------
// Main kernel. Block = 256 threads = 8 warps, one u, 8 consecutive b.
// Per chain: S_p = sum_{d0,d1} x[2p,d0] x[2p+1,d1] KK_p[d0,d1]  (4 builds,
// block-cooperative, KK loaded once per block), then
// out = trace(S0 S1 S2 S3) = sum_{i,j} A[i,j] * B[j,i],  A=S0@S1, B=S2@S3.
// S0 -> pitch-33 smem (row reads); S1,S2,S3 -> row-major (broadcast/column).
// ---------------------------------------------------------------------------
#define SLPITCH 1056          // floats per b: 32 rows * 33
#define SMEM_FLOATS (256 + 8 * SLPITCH + 8 * 1024)

// build one S_p for all 8 b's.  mode: 0 = pitch-33 scalar stores (dstL),
// 1 = row-major ulonglong2 stores (dst)
static __device__ __forceinline__ void build_stage(
    int u, int p, int tid, const float* Xs, float* dstBase, int dstPitchFloats, int mode)
{
    const ulonglong2* kkbase =
        (const ulonglong2*)(g_KK + (size_t)((u * 4 + p) * 16) * 1024);
    ulonglong2 kk[16];
    #pragma unroll
    for (int c = 0; c < 16; c++) kk[c] = kkbase[c * 256 + tid];   // coalesced

    const int j = tid >> 3, k4 = tid & 7;
    #pragma unroll 1
    for (int b = 0; b < 8; b++) {
        const float4 xa = ((const float4*)Xs)[b * 8 + 2 * p];
        const float4 xb = ((const float4*)Xs)[b * 8 + 2 * p + 1];
        const ull xb0 = pk2(xb.x, xb.x), xb1 = pk2(xb.y, xb.y);
        const ull xb2 = pk2(xb.z, xb.z), xb3 = pk2(xb.w, xb.w);
        const float xaf[4] = {xa.x, xa.y, xa.z, xa.w};
        ull accx = 0ull, accy = 0ull;
        #pragma unroll
        for (int d0 = 0; d0 < 4; d0++) {
            ull ix = mul2_(xb0, kk[d0 * 4 + 0].x);
            ull iy = mul2_(xb0, kk[d0 * 4 + 0].y);
            ix = fma2_(xb1, kk[d0 * 4 + 1].x, ix);
            iy = fma2_(xb1, kk[d0 * 4 + 1].y, iy);
            ix = fma2_(xb2, kk[d0 * 4 + 2].x, ix);
            iy = fma2_(xb2, kk[d0 * 4 + 2].y, iy);
            ix = fma2_(xb3, kk[d0 * 4 + 3].x, ix);
            iy = fma2_(xb3, kk[d0 * 4 + 3].y, iy);
            const ull a2 = pk2(xaf[d0], xaf[d0]);
            accx = fma2_(a2, ix, accx);
            accy = fma2_(a2, iy, accy);
        }
        if (mode == 0) {
            float s0, s1, s2, s3;
            upk2(accx, s0, s1); upk2(accy, s2, s3);
            float* dl = dstBase + b * dstPitchFloats + j * 33 + k4 * 4;
            dl[0] = s0; dl[1] = s1; dl[2] = s2; dl[3] = s3;
        } else {
            ulonglong2 v; v.x = accx; v.y = accy;
            ((ulonglong2*)(dstBase + b * dstPitchFloats))[tid] = v;
        }
    }
}

__global__ __launch_bounds__(256) void ring_main(const float* __restrict__ X,
                                                 float* __restrict__ out) {
    extern __shared__ float smem[];
    float* Xs = smem;                       // 256 floats
    float* SL = smem + 256;                 // 8 * 1056  (S0 pitch-33, later S2 row-major)
    float* SR = smem + 256 + 8 * SLPITCH;   // 8 * 1024  (S1, later S3 row-major)

    const int tid = threadIdx.x, w = tid >> 5, lane = tid & 31;
    const int u = blockIdx.x >> 6;
    const int b0 = (blockIdx.x & 63) * 8;

    Xs[tid] = X[b0 * 32 + tid];
    __syncthreads();

    // ---- build S0 (pitch-33) and S1 (row-major) ----
    build_stage(u, 0, tid, Xs, SL, SLPITCH, 0);
    build_stage(u, 1, tid, Xs, SR, 1024, 1);
    __syncthreads();

    // ---- mm1: A = S0 @ S1 (this warp's b = w), A rows in registers ----
    float m[32];
    {
        const float* s0 = SL + w * SLPITCH + lane * 33;
        #pragma unroll
        for (int j = 0; j < 32; j++) m[j] = s0[j];       // conflict-free
    }
    ull acc[16];
    #pragma unroll
    for (int q = 0; q < 16; q++) acc[q] = 0ull;
    {
        const ulonglong2* s1 = (const ulonglong2*)(SR + w * 1024);
        #pragma unroll
        for (int j = 0; j < 32; j++) {
            const ull mj = pk2(m[j], m[j]);
            #pragma unroll
            for (int q = 0; q < 8; q++) {
                const ulonglong2 rv = s1[j * 8 + q];     // broadcast
                acc[2 * q]     = fma2_(mj, rv.x, acc[2 * q]);
                acc[2 * q + 1] = fma2_(mj, rv.y, acc[2 * q + 1]);
            }
        }
    }
    float A_[32];
    #pragma unroll
    for (int q = 0; q < 16; q++) upk2(acc[q], A_[2 * q], A_[2 * q + 1]);

    __syncthreads();   // everyone done reading S0/S1 before rebuild

    // ---- build S2 (row-major into SL) and S3 (row-major into SR) ----
    build_stage(u, 2, tid, Xs, SL, SLPITCH, 1);
    build_stage(u, 3, tid, Xs, SR, 1024, 1);
    __syncthreads();

    // ---- mm2 + trace:  result = sum_j A[.,j] * B[j,.],  B = S2 @ S3
    // lane i holds A row i; compute B column i: B[j,i] = sum_k S2[j,k]*S3[k,i]
    ull v2[16];
    {
        const float* s3 = SR + w * 1024;
        float v[32];
        #pragma unroll
        for (int k = 0; k < 32; k++) v[k] = s3[k * 32 + lane];   // conflict-free column
        #pragma unroll
        for (int q = 0; q < 16; q++) v2[q] = pk2(v[2 * q], v[2 * q + 1]);
    }
    float pacc = 0.f;
    {
        const ulonglong2* s2 = (const ulonglong2*)(SL + w * SLPITCH);
        #pragma unroll
        for (int j = 0; j < 32; j++) {
            ull t = 0ull;
            #pragma unroll
            for (int q = 0; q < 8; q++) {
                const ulonglong2 rv = s2[j * 8 + q];    // broadcast
                t = fma2_(rv.x, v2[2 * q], t);
                t = fma2_(rv.y, v2[2 * q + 1], t);
            }
            float tl, th; upk2(t, tl, th);
            pacc = fmaf(A_[j], tl + th, pacc);
        }
    }
    #pragma unroll
    for (int o = 16; o; o >>= 1)
        pacc += __shfl_xor_sync(0xffffffffu, pacc, o);
    if (lane == 0) out[(b0 + w) * 64 + u] = pacc;
}

extern "C" void kernel_launch(void* const* d_in, const int* in_sizes, int n_in,
                              void* d_out, int out_size) {
    const float* X = (const float*)d_in[0];
    const float* K = (const float*)d_in[1];
    if (in_sizes[0] != B_ * F_ * D_) {
        X = (const float*)d_in[1];
        K = (const float*)d_in[0];
    }
    cudaFuncSetAttribute(ring_main, cudaFuncAttributeMaxDynamicSharedMemorySize,
                         SMEM_FLOATS * 4);
    kk_precompute<<<256, 256>>>(K);
    ring_main<<<64 * 64, 256, SMEM_FLOATS * 4>>>(X, (float*)d_out);
}

// round 3
// speedup vs baseline: 2.3835x; 1.1402x over previous
#include <cuda_runtime.h>

#define D_ 4
#define R_ 32
#define F_ 8
#define U_ 64
#define B_ 512

typedef unsigned long long ull;

// ---------- packed f32x2 helpers (SASS FFMA2) ----------
static __device__ __forceinline__ ull pk2(float lo, float hi) {
    ull r; asm("mov.b64 %0, {%1, %2};" : "=l"(r) : "f"(lo), "f"(hi)); return r;
}
static __device__ __forceinline__ void upk2(ull v, float& lo, float& hi) {
    asm("mov.b64 {%0, %1}, %2;" : "=f"(lo), "=f"(hi) : "l"(v));
}
static __device__ __forceinline__ ull fma2_(ull a, ull b, ull c) {
    ull d; asm("fma.rn.f32x2 %0, %1, %2, %3;" : "=l"(d) : "l"(a), "l"(b), "l"(c)); return d;
}
static __device__ __forceinline__ ull mul2_(ull a, ull b) {
    ull d; asm("mul.rn.f32x2 %0, %1, %2;" : "=l"(d) : "l"(a), "l"(b)); return d;
}

// Pair-merged products: g_KK[u][p][c=(d0*4+d1)][j*32+k]
__device__ float g_KK[U_ * 4 * 16 * 1024];   // 16 MB

// ---------------------------------------------------------------------------
// Precompute: 256 blocks = (u,p), 512 threads = 16 warps, warp w computes c=w.
// ---------------------------------------------------------------------------
__global__ __launch_bounds__(512) void kk_precompute(const float* __restrict__ K) {
    __shared__ float As[4][33 * 32];
    __shared__ float Bs[4][1024];
    const int u = blockIdx.x >> 2;
    const int p = blockIdx.x & 3;
    const int tid = threadIdx.x;

    for (int d = 0; d < 4; d++)
        for (int e = tid; e < 1024; e += 512) {
            As[d][(e >> 5) * 33 + (e & 31)] = K[((d * 1024 + e) * 8 + 2 * p) * 64 + u];
            Bs[d][e]                        = K[((d * 1024 + e) * 8 + 2 * p + 1) * 64 + u];
        }
    __syncthreads();

    const int c = tid >> 5, lane = tid & 31;
    const int d0 = c >> 2, d1 = c & 3;
    ull acc[16];
    #pragma unroll
    for (int q = 0; q < 16; q++) acc[q] = 0ull;
    const float* arow = &As[d0][lane * 33];
    const ulonglong2* bmat = (const ulonglong2*)Bs[d1];
    #pragma unroll
    for (int j = 0; j < 32; j++) {
        const ull a2 = pk2(arow[j], arow[j]);
        #pragma unroll
        for (int q = 0; q < 8; q++) {
            const ulonglong2 bv = bmat[j * 8 + q];   // broadcast
            acc[2 * q]     = fma2_(a2, bv.x, acc[2 * q]);
            acc[2 * q + 1] = fma2_(a2, bv.y, acc[2 * q + 1]);
        }
    }
    float4* dst = (float4*)(g_KK + (((u * 4 + p) * 16 + c) * 1024) + lane * 32);
    #pragma unroll
    for (int q = 0; q < 8; q++) {
        float4 o;
        upk2(acc[2 * q],     o.x, o.y);
        upk2(acc[2 * q + 1], o.z, o.w);
        dst[q] = o;
    }
}

// ---------------------------------------------------------------------------
// Main. Block = 256 threads = 8 warps, one u, 8 b (warp w owns b = b0+w).
// Smem (floats): Xs[256] | W[512] | SL[8*1152] | SR[8*1152] | As[8*1152]
// S0,S1,S3,A stored pitch 36 (float4 rows); S2 stored TRANSPOSED pitch 33.
// ---------------------------------------------------------------------------
#define PITCH 36
#define SLOT  1152            // 32*36 per b
#define OFF_W   256
#define OFF_SL  768
#define OFF_SR  (OFF_SL + 8 * SLOT)
#define OFF_AS  (OFF_SR + 8 * SLOT)
#define SMEM_FLOATS (OFF_AS + 8 * SLOT)

// Build S_p for all 8 b's. MODE 0: pitch-36 float4 row-major.
// MODE 1: transposed, pitch-33, scalar stores (for S2).
template <int MODE>
static __device__ __forceinline__ void build_stage(int u, int p, int tid,
                                                   const float* Wsm, float* dst) {
    const ulonglong2* kkbase =
        (const ulonglong2*)(g_KK + (size_t)((u * 4 + p) * 16) * 1024);
    ulonglong2 kk[16];
    #pragma unroll
    for (int c = 0; c < 16; c++) kk[c] = kkbase[c * 256 + tid];   // coalesced

    const int j = tid >> 3, k4 = tid & 7;
    #pragma unroll 2
    for (int b = 0; b < 8; b++) {
        float4 wv[4];
        #pragma unroll
        for (int q = 0; q < 4; q++)
            wv[q] = ((const float4*)(Wsm + (b * 4 + p) * 16))[q];   // broadcast
        const float* wf = (const float*)wv;
        ull accx = 0ull, accy = 0ull;
        #pragma unroll
        for (int c = 0; c < 16; c++) {
            const ull w2 = pk2(wf[c], wf[c]);
            accx = fma2_(w2, kk[c].x, accx);
            accy = fma2_(w2, kk[c].y, accy);
        }
        if (MODE == 0) {
            float4 o;
            upk2(accx, o.x, o.y); upk2(accy, o.z, o.w);
            *(float4*)(dst + b * SLOT + j * PITCH + 4 * k4) = o;
        } else {
            float s0, s1, s2, s3;
            upk2(accx, s0, s1); upk2(accy, s2, s3);
            float* base = dst + b * SLOT + j;          // transposed: [col][row]
            base[(4 * k4 + 0) * 33] = s0;
            base[(4 * k4 + 1) * 33] = s1;
            base[(4 * k4 + 2) * 33] = s2;
            base[(4 * k4 + 3) * 33] = s3;
        }
    }
}

// Register-tiled 32x32x32 matmul: C = A @ B, both operands pitch-36 in smem.
// Lane (r = lane>>2, c = lane&3) computes rows {r,r+8,r+16,r+24} x cols
// {8c..8c+7}; acc packed as f32x2 over column pairs.
static __device__ __forceinline__ void mmk(const float* A, const float* B,
                                           int r, int c, ull acc[4][4]) {
    #pragma unroll
    for (int i = 0; i < 16; i++) ((ull*)acc)[i] = 0ull;
    #pragma unroll
    for (int k4 = 0; k4 < 8; k4++) {
        float4 av[4];
        #pragma unroll
        for (int rho = 0; rho < 4; rho++)
            av[rho] = *(const float4*)(A + (r + 8 * rho) * PITCH + 4 * k4);
        ulonglong2 bv[4][2];
        #pragma unroll
        for (int kp = 0; kp < 4; kp++) {
            bv[kp][0] = *(const ulonglong2*)(B + (4 * k4 + kp) * PITCH + 8 * c);
            bv[kp][1] = *(const ulonglong2*)(B + (4 * k4 + kp) * PITCH + 8 * c + 4);
        }
        #pragma unroll
        for (int rho = 0; rho < 4; rho++) {
            const float* af = (const float*)&av[rho];
            #pragma unroll
            for (int kp = 0; kp < 4; kp++) {
                const ull a2 = pk2(af[kp], af[kp]);
                acc[rho][0] = fma2_(a2, bv[kp][0].x, acc[rho][0]);
                acc[rho][1] = fma2_(a2, bv[kp][0].y, acc[rho][1]);
                acc[rho][2] = fma2_(a2, bv[kp][1].x, acc[rho][2]);
                acc[rho][3] = fma2_(a2, bv[kp][1].y, acc[rho][3]);
            }
        }
    }
}

__global__ __launch_bounds__(256, 2) void ring_main(const float* __restrict__ X,
                                                    float* __restrict__ out) {
    extern __shared__ float smem[];
    float* Xs = smem;
    float* Wsm = smem + OFF_W;
    float* SL = smem + OFF_SL;
    float* SR = smem + OFF_SR;
    float* Asm = smem + OFF_AS;

    const int tid = threadIdx.x, w = tid >> 5, lane = tid & 31;
    const int r = lane >> 2, c = lane & 3;
    const int u = blockIdx.x >> 6;
    const int b0 = (blockIdx.x & 63) * 8;

    Xs[tid] = X[b0 * 32 + tid];
    __syncthreads();
    // W[b][p][c=(d0,d1)] = x[2p,d0] * x[2p+1,d1]
    #pragma unroll
    for (int e = tid; e < 512; e += 256) {
        const int bb = e >> 6, pp = (e >> 4) & 3, cc = e & 15;
        Wsm[e] = Xs[bb * 32 + 2 * pp * 4 + (cc >> 2)] *
                 Xs[bb * 32 + (2 * pp + 1) * 4 + (cc & 3)];
    }
    __syncthreads();

    // ---- S0 -> SL (pitch36), S1 -> SR (pitch36)
    build_stage<0>(u, 0, tid, Wsm, SL);
    build_stage<0>(u, 1, tid, Wsm, SR);
    __syncthreads();

    // ---- A = S0 @ S1, store to Asm (this warp's b)
    {
        ull acc[4][4];
        mmk(SL + w * SLOT, SR + w * SLOT, r, c, acc);
        float* dst = Asm + w * SLOT;
        #pragma unroll
        for (int rho = 0; rho < 4; rho++) {
            float4 o0, o1;
            upk2(acc[rho][0], o0.x, o0.y); upk2(acc[rho][1], o0.z, o0.w);
            upk2(acc[rho][2], o1.x, o1.y); upk2(acc[rho][3], o1.z, o1.w);
            *(float4*)(dst + (r + 8 * rho) * PITCH + 8 * c)     = o0;
            *(float4*)(dst + (r + 8 * rho) * PITCH + 8 * c + 4) = o1;
        }
    }
    __syncthreads();   // all warps done reading SL/SR

    // ---- S2 -> SL transposed (pitch33), S3 -> SR (pitch36)
    build_stage<1>(u, 2, tid, Wsm, SL);
    build_stage<0>(u, 3, tid, Wsm, SR);
    __syncthreads();

    // ---- D = S3 @ A ; out = sum_{j,k} S2[j,k] * D[k,j] = sum S2T[k][j]*D[k,j]
    {
        ull acc[4][4];
        mmk(SR + w * SLOT, Asm + w * SLOT, r, c, acc);
        const float* s2t = SL + w * SLOT;
        float pacc = 0.f;
        #pragma unroll
        for (int rho = 0; rho < 4; rho++) {
            const float* row = s2t + (r + 8 * rho) * 33 + 8 * c;
            #pragma unroll
            for (int gp = 0; gp < 4; gp++) {
                float d0, d1;
                upk2(acc[rho][gp], d0, d1);
                pacc = fmaf(d0, row[2 * gp], pacc);
                pacc = fmaf(d1, row[2 * gp + 1], pacc);
            }
        }
        #pragma unroll
        for (int o = 16; o; o >>= 1)
            pacc += __shfl_xor_sync(0xffffffffu, pacc, o);
        if (lane == 0) out[(b0 + w) * 64 + u] = pacc;
    }
}

extern "C" void kernel_launch(void* const* d_in, const int* in_sizes, int n_in,
                              void* d_out, int out_size) {
    const float* X = (const float*)d_in[0];
    const float* K = (const float*)d_in[1];
    if (in_sizes[0] != B_ * F_ * D_) {
        X = (const float*)d_in[1];
        K = (const float*)d_in[0];
    }
    cudaFuncSetAttribute(ring_main, cudaFuncAttributeMaxDynamicSharedMemorySize,
                         SMEM_FLOATS * 4);
    kk_precompute<<<256, 512>>>(K);
    ring_main<<<64 * 64, 256, SMEM_FLOATS * 4>>>(X, (float*)d_out);
}